// round 14
// baseline (speedup 1.0000x reference)
#include <cuda_runtime.h>
#include <cuda_fp16.h>

#define NN 100000
#define NE 2500000
#define NG 1000
#define HD 32
#define SCAN_B 512
#define NB ((NN + SCAN_B - 1) / SCAN_B)   // 196

// ---- scratch (__device__ globals; allocation-free) ----
__device__ int   g_is64;
__device__ __align__(16) float  g_deg[NN];        // dinv (written by k_prep)
__device__ __align__(16) int    g_cnt[NN];
__device__ __align__(16) int    g_scani[NN];
__device__ __align__(16) int    g_bsum[256];
__device__ __align__(16) int    g_off[NN];
__device__ __align__(16) int    g_cur[NN];
__device__ __align__(16) int2   g_csr[NE];        // {src, packed half2{w,w}}
__device__ __align__(16) float4 g_x[NN];          // dinv[i] * x[i]
__device__ __align__(16) __half g_Ah[NN * HD];    // fp16 prescaled features
__device__ __align__(16) __half g_Bh[NN * HD];
__device__ __align__(16) float  g_gsum[NG * HD];
__device__ __align__(16) float  g_gcnt[NG];

__device__ __forceinline__ int ldidx(const void* p, long long e) {
    if (g_is64) return (int)((const long long*)p)[e];
    return ((const int*)p)[e];
}

__global__ void k_init(const void* ei) {
    int t = blockIdx.x * blockDim.x + threadIdx.x;
    if (t == 0) {
        const int* p = (const int*)ei;
        int z = 0;
#pragma unroll
        for (int j = 1; j < 64; j += 2) z |= p[j];
        g_is64 = (z == 0) ? 1 : 0;
    }
    if (t < NN) g_cnt[t] = 0;
    if (t < NG * HD) g_gsum[t] = 0.f;
    if (t < NG) g_gcnt[t] = 0.f;
}

__global__ void k_hist(const void* __restrict__ ei) {
    int e = blockIdx.x * blockDim.x + threadIdx.x;
    if (e >= NE) return;
    int c = ldidx(ei, (long long)NE + e);
    atomicAdd(&g_cnt[c], 1);
}

__global__ void k_scan1() {
    __shared__ int s[SCAN_B];
    int tid = threadIdx.x;
    int i = blockIdx.x * SCAN_B + tid;
    s[tid] = (i < NN) ? g_cnt[i] : 0;
    __syncthreads();
#pragma unroll
    for (int off = 1; off < SCAN_B; off <<= 1) {
        int v = (tid >= off) ? s[tid - off] : 0;
        __syncthreads();
        s[tid] += v;
        __syncthreads();
    }
    if (i < NN) g_scani[i] = s[tid];
    if (tid == SCAN_B - 1) g_bsum[blockIdx.x] = s[tid];
}

// merged scan2+scan3
__global__ void k_scan23() {
    __shared__ int s[256];
    int tid = threadIdx.x;
    s[tid] = (tid < NB) ? g_bsum[tid] : 0;
    __syncthreads();
#pragma unroll
    for (int off = 1; off < 256; off <<= 1) {
        int v = (tid >= off) ? s[tid - off] : 0;
        __syncthreads();
        s[tid] += v;
        __syncthreads();
    }
    int i = blockIdx.x * blockDim.x + tid;
    if (i >= NN) return;
    int b = i / SCAN_B;
    int add = (b > 0) ? s[b - 1] : 0;
    int excl = add + g_scani[i] - g_cnt[i];
    g_off[i] = excl;
    g_cur[i] = excl;
}

// CSR fill: weight packed once as half2{w,w}
__global__ void k_fill(const void* __restrict__ ei, const float* __restrict__ ew) {
    int e = blockIdx.x * blockDim.x + threadIdx.x;
    if (e >= NE) return;
    int r = ldidx(ei, e);
    int c = ldidx(ei, (long long)NE + e);
    int p = atomicAdd(&g_cur[c], 1);
    float w = ew[e];
    __half2 wp = __floats2half2_rn(w, w);
    g_csr[p] = make_int2(r, *reinterpret_cast<int*>(&wp));
}

// warp per node: deg = coalesced bucket sum, dinv, prescale x.
__global__ void k_prep(const float* __restrict__ x) {
    int t = blockIdx.x * blockDim.x + threadIdx.x;
    int i = t >> 5, lane = t & 31;
    if (i >= NN) return;
    int beg = g_off[i];
    int cnt = g_cnt[i];
    float s = 0.f;
    for (int e = lane; e < cnt; e += 32) {
        int wb = g_csr[beg + e].y;
        s += __low2float(*reinterpret_cast<__half2*>(&wb));
    }
#pragma unroll
    for (int d = 1; d < 32; d <<= 1)
        s += __shfl_xor_sync(0xffffffffu, s, d);
    float dv = rsqrtf(s + 1.0f);
    if (lane == 0) {
        g_deg[i] = dv;
        float4 xi = __ldg(&reinterpret_cast<const float4*>(x)[i]);
        g_x[i] = make_float4(dv * xi.x, dv * xi.y, dv * xi.z, dv * xi.w);
    }
}

// Layer 1: gather prescaled 16B fp32 x rows (lane-strided);
// h1 = relu(dv*(sum+self)@W1+b1); store g_Bh[i] = fp16(dv * (h1@W2)).
__global__ void k_layer1(const float* __restrict__ W1, const float* __restrict__ b1,
                         const float* __restrict__ W2) {
    __shared__ float W1s[4 * HD];
    __shared__ float W2s[HD * HD];
    int tid = threadIdx.x;
    for (int k = tid; k < 4 * HD; k += blockDim.x)  W1s[k] = W1[k];
    for (int k = tid; k < HD * HD; k += blockDim.x) W2s[k] = W2[k];
    __syncthreads();
    int t = blockIdx.x * blockDim.x + tid;
    int i = t >> 5, lane = t & 31;
    if (i >= NN) return;

    int beg = g_off[i];
    int cnt = g_cnt[i];
    float4 acc = make_float4(0.f, 0.f, 0.f, 0.f);
    for (int e = lane; e < cnt; e += 32) {
        int2 ce = g_csr[beg + e];
        float w = __low2float(*reinterpret_cast<__half2*>(&ce.y));
        float4 xv = g_x[ce.x];
        acc.x = fmaf(w, xv.x, acc.x);
        acc.y = fmaf(w, xv.y, acc.y);
        acc.z = fmaf(w, xv.z, acc.z);
        acc.w = fmaf(w, xv.w, acc.w);
    }
#pragma unroll
    for (int d = 1; d < 32; d <<= 1) {
        acc.x += __shfl_xor_sync(0xffffffffu, acc.x, d);
        acc.y += __shfl_xor_sync(0xffffffffu, acc.y, d);
        acc.z += __shfl_xor_sync(0xffffffffu, acc.z, d);
        acc.w += __shfl_xor_sync(0xffffffffu, acc.w, d);
    }
    float4 xi = g_x[i];
    float dv = g_deg[i];
    acc.x = (acc.x + xi.x) * dv;
    acc.y = (acc.y + xi.y) * dv;
    acc.z = (acc.z + xi.z) * dv;
    acc.w = (acc.w + xi.w) * dv;

    float h = __ldg(&b1[lane]);
    h = fmaf(acc.x, W1s[0 * HD + lane], h);
    h = fmaf(acc.y, W1s[1 * HD + lane], h);
    h = fmaf(acc.z, W1s[2 * HD + lane], h);
    h = fmaf(acc.w, W1s[3 * HD + lane], h);
    h = fmaxf(h, 0.f);

    float o = 0.f;
#pragma unroll
    for (int k = 0; k < HD; k++) {
        float hk = __shfl_sync(0xffffffffu, h, k);
        o = fmaf(hk, W2s[k * HD + lane], o);
    }
    g_Bh[(size_t)i * HD + lane] = __float2half_rn(dv * o);
}

// HFMA2 fp16 gather, deep-MLP version: warp = 4 edge-groups x 8 lanes.
// Main loop: 16 edges/iter with FOUR independent chains (8 loads in flight),
// then 8-edge, 4-edge, and clamped tail. Returns (sum + self) replicated.
__device__ __forceinline__ float4 gather_node_h2(const uint2* __restrict__ src, int i,
                                                 int grp, int sub) {
    int beg = g_off[i];
    int cnt = g_cnt[i];
    const __half2 hz = __floats2half2_rn(0.f, 0.f);
    __half2 a01 = hz, a23 = hz, b01 = hz, b23 = hz;
    __half2 c01 = hz, c23 = hz, d01 = hz, d23 = hz;
    int e = 0;
    for (; e + 16 <= cnt; e += 16) {
        int2 ce0 = g_csr[beg + e + grp];
        int2 ce1 = g_csr[beg + e + 4 + grp];
        int2 ce2 = g_csr[beg + e + 8 + grp];
        int2 ce3 = g_csr[beg + e + 12 + grp];
        uint2 u0 = src[(size_t)ce0.x * 8 + sub];
        uint2 u1 = src[(size_t)ce1.x * 8 + sub];
        uint2 u2 = src[(size_t)ce2.x * 8 + sub];
        uint2 u3 = src[(size_t)ce3.x * 8 + sub];
        __half2 w0 = *reinterpret_cast<__half2*>(&ce0.y);
        __half2 w1 = *reinterpret_cast<__half2*>(&ce1.y);
        __half2 w2 = *reinterpret_cast<__half2*>(&ce2.y);
        __half2 w3 = *reinterpret_cast<__half2*>(&ce3.y);
        a01 = __hfma2(w0, *reinterpret_cast<__half2*>(&u0.x), a01);
        a23 = __hfma2(w0, *reinterpret_cast<__half2*>(&u0.y), a23);
        b01 = __hfma2(w1, *reinterpret_cast<__half2*>(&u1.x), b01);
        b23 = __hfma2(w1, *reinterpret_cast<__half2*>(&u1.y), b23);
        c01 = __hfma2(w2, *reinterpret_cast<__half2*>(&u2.x), c01);
        c23 = __hfma2(w2, *reinterpret_cast<__half2*>(&u2.y), c23);
        d01 = __hfma2(w3, *reinterpret_cast<__half2*>(&u3.x), d01);
        d23 = __hfma2(w3, *reinterpret_cast<__half2*>(&u3.y), d23);
    }
    if (e + 8 <= cnt) {
        int2 ce0 = g_csr[beg + e + grp];
        int2 ce1 = g_csr[beg + e + 4 + grp];
        uint2 u0 = src[(size_t)ce0.x * 8 + sub];
        uint2 u1 = src[(size_t)ce1.x * 8 + sub];
        __half2 w0 = *reinterpret_cast<__half2*>(&ce0.y);
        __half2 w1 = *reinterpret_cast<__half2*>(&ce1.y);
        a01 = __hfma2(w0, *reinterpret_cast<__half2*>(&u0.x), a01);
        a23 = __hfma2(w0, *reinterpret_cast<__half2*>(&u0.y), a23);
        b01 = __hfma2(w1, *reinterpret_cast<__half2*>(&u1.x), b01);
        b23 = __hfma2(w1, *reinterpret_cast<__half2*>(&u1.y), b23);
        e += 8;
    }
    if (e + 4 <= cnt) {
        int2 ce = g_csr[beg + e + grp];
        __half2 w = *reinterpret_cast<__half2*>(&ce.y);
        uint2 u = src[(size_t)ce.x * 8 + sub];
        c01 = __hfma2(w, *reinterpret_cast<__half2*>(&u.x), c01);
        c23 = __hfma2(w, *reinterpret_cast<__half2*>(&u.y), c23);
        e += 4;
    }
    int rem = cnt - e;                           // 0..3
    if (rem > 0) {
        int g2 = min(grp, rem - 1);              // clamp: valid load, zero weight
        int2 ce = g_csr[beg + e + g2];
        int wb = (grp < rem) ? ce.y : 0;
        __half2 w = *reinterpret_cast<__half2*>(&wb);
        uint2 u = src[(size_t)ce.x * 8 + sub];
        d01 = __hfma2(w, *reinterpret_cast<__half2*>(&u.x), d01);
        d23 = __hfma2(w, *reinterpret_cast<__half2*>(&u.y), d23);
    }
    // convert chains to fp32 and combine (each chain held <= 2 rounded terms)
    float2 fa01 = __half22float2(a01), fa23 = __half22float2(a23);
    float2 fb01 = __half22float2(b01), fb23 = __half22float2(b23);
    float2 fc01 = __half22float2(c01), fc23 = __half22float2(c23);
    float2 fd01 = __half22float2(d01), fd23 = __half22float2(d23);
    float4 acc = make_float4((fa01.x + fb01.x) + (fc01.x + fd01.x),
                             (fa01.y + fb01.y) + (fc01.y + fd01.y),
                             (fa23.x + fb23.x) + (fc23.x + fd23.x),
                             (fa23.y + fb23.y) + (fc23.y + fd23.y));
#pragma unroll
    for (int d = 8; d <= 16; d <<= 1) {          // reduce across the 4 groups
        acc.x += __shfl_xor_sync(0xffffffffu, acc.x, d);
        acc.y += __shfl_xor_sync(0xffffffffu, acc.y, d);
        acc.z += __shfl_xor_sync(0xffffffffu, acc.z, d);
        acc.w += __shfl_xor_sync(0xffffffffu, acc.w, d);
    }
    uint2 us = src[(size_t)i * 8 + sub];         // self row (prescaled)
    float2 s01 = __half22float2(*reinterpret_cast<__half2*>(&us.x));
    float2 s23 = __half22float2(*reinterpret_cast<__half2*>(&us.y));
    acc.x += s01.x; acc.y += s01.y; acc.z += s23.x; acc.w += s23.y;
    return acc;
}

// Layer 2: gather g_Bh; v = relu(dv*acc + b2); o = v@W3; g_Ah = fp16(dv*o).
__global__ void k_layer2(const float* __restrict__ bias, const float* __restrict__ W) {
    __shared__ float4 Ws[HD * 8];                 // W[k][f] as float4: Ws[k*8 + sub]
    int tid = threadIdx.x;
    for (int k = tid; k < HD * 8; k += blockDim.x)
        Ws[k] = reinterpret_cast<const float4*>(W)[k];
    __syncthreads();
    int t = blockIdx.x * blockDim.x + tid;
    int i = t >> 5, lane = t & 31, grp = lane >> 3, sub = lane & 7;
    if (i >= NN) return;

    float4 v = gather_node_h2(reinterpret_cast<const uint2*>(g_Bh), i, grp, sub);
    float dv = g_deg[i];
    float4 b4 = __ldg(&reinterpret_cast<const float4*>(bias)[sub]);
    v.x = fmaxf(fmaf(v.x, dv, b4.x), 0.f);
    v.y = fmaxf(fmaf(v.y, dv, b4.y), 0.f);
    v.z = fmaxf(fmaf(v.z, dv, b4.z), 0.f);
    v.w = fmaxf(fmaf(v.w, dv, b4.w), 0.f);

    float4 o = make_float4(0.f, 0.f, 0.f, 0.f);
#pragma unroll
    for (int j = 0; j < 8; j++) {
        int srcLane = grp * 10 + (j >> 2);        // = grp*8 + ((grp*8+j)>>2)
        float comp = ((j & 3) == 0) ? v.x : ((j & 3) == 1) ? v.y
                   : ((j & 3) == 2) ? v.z : v.w;
        float vk = __shfl_sync(0xffffffffu, comp, srcLane);
        float4 w4 = Ws[(grp * 8 + j) * 8 + sub];
        o.x = fmaf(vk, w4.x, o.x); o.y = fmaf(vk, w4.y, o.y);
        o.z = fmaf(vk, w4.z, o.z); o.w = fmaf(vk, w4.w, o.w);
    }
#pragma unroll
    for (int d = 8; d <= 16; d <<= 1) {
        o.x += __shfl_xor_sync(0xffffffffu, o.x, d);
        o.y += __shfl_xor_sync(0xffffffffu, o.y, d);
        o.z += __shfl_xor_sync(0xffffffffu, o.z, d);
        o.w += __shfl_xor_sync(0xffffffffu, o.w, d);
    }
    if (grp == 0) {
        __half2 p0 = __floats2half2_rn(dv * o.x, dv * o.y);
        __half2 p1 = __floats2half2_rn(dv * o.z, dv * o.w);
        uint2 st;
        st.x = *reinterpret_cast<unsigned*>(&p0);
        st.y = *reinterpret_cast<unsigned*>(&p1);
        reinterpret_cast<uint2*>(g_Ah)[(size_t)i * 8 + sub] = st;
    }
}

// Layer 3: gather g_Ah; v = dv*acc + b3; sorted-batch mean-pool.
__global__ void k_gather_pool(const float* __restrict__ bias,
                              const void* __restrict__ batch) {
    __shared__ float s[8][HD];
    __shared__ int sg[8];
    int tid = threadIdx.x;
    int t = blockIdx.x * blockDim.x + tid;
    int i = t >> 5, lane = t & 31, grp = lane >> 3, sub = lane & 7;
    int warpid = tid >> 5;
    float4 v = gather_node_h2(reinterpret_cast<const uint2*>(g_Ah), i, grp, sub);
    float dv = g_deg[i];
    float4 b4 = __ldg(&reinterpret_cast<const float4*>(bias)[sub]);
    v.x = fmaf(v.x, dv, b4.x);
    v.y = fmaf(v.y, dv, b4.y);
    v.z = fmaf(v.z, dv, b4.z);
    v.w = fmaf(v.w, dv, b4.w);
    if (grp == 0)
        *reinterpret_cast<float4*>(&s[warpid][sub * 4]) = v;
    if (lane == 0) sg[warpid] = ldidx(batch, i);
    __syncthreads();
    if (tid < HD) {
        int g0 = sg[0];
        if (g0 == sg[7]) {                        // sorted => all 8 equal
            float sum = 0.f;
#pragma unroll
            for (int w = 0; w < 8; w++) sum += s[w][tid];
            atomicAdd(&g_gsum[g0 * HD + tid], sum);
            if (tid == 0) atomicAdd(&g_gcnt[g0], 8.0f);
        } else {
#pragma unroll
            for (int w = 0; w < 8; w++)
                atomicAdd(&g_gsum[sg[w] * HD + tid], s[w][tid]);
            if (tid == 0) {
#pragma unroll
                for (int w = 0; w < 8; w++) atomicAdd(&g_gcnt[sg[w]], 1.0f);
            }
        }
    }
}

__global__ void k_head(const float* __restrict__ lw, const float* __restrict__ lb,
                       float* __restrict__ out) {
    int g = blockIdx.x * blockDim.x + threadIdx.x;
    if (g >= NG) return;
    float inv = 1.0f / fmaxf(g_gcnt[g], 1.0f);
    float l0 = __ldg(&lb[0]), l1 = __ldg(&lb[1]), l2 = __ldg(&lb[2]);
#pragma unroll 8
    for (int k = 0; k < HD; k++) {
        float p = g_gsum[g * HD + k] * inv;
        l0 += p * __ldg(&lw[k * 3 + 0]);
        l1 += p * __ldg(&lw[k * 3 + 1]);
        l2 += p * __ldg(&lw[k * 3 + 2]);
    }
    float m = fmaxf(l0, fmaxf(l1, l2));
    float e0 = expf(l0 - m), e1 = expf(l1 - m), e2 = expf(l2 - m);
    float s = 1.0f / (e0 + e1 + e2);
    out[g * 3 + 0] = e0 * s;
    out[g * 3 + 1] = e1 * s;
    out[g * 3 + 2] = e2 * s;
}

extern "C" void kernel_launch(void* const* d_in, const int* in_sizes, int n_in,
                              void* d_out, int out_size) {
    const float* x     = (const float*)d_in[0];
    const void*  ei    = d_in[1];
    const float* ew    = (const float*)d_in[2];
    const void*  batch = d_in[3];
    const float* W1    = (const float*)d_in[4];
    const float* b1    = (const float*)d_in[5];
    const float* W2    = (const float*)d_in[6];
    const float* b2    = (const float*)d_in[7];
    const float* W3    = (const float*)d_in[8];
    const float* b3    = (const float*)d_in[9];
    const float* lw    = (const float*)d_in[10];
    const float* lb    = (const float*)d_in[11];
    float* out = (float*)d_out;

    const int B = 256;
    const int gbN  = (NN + B - 1) / B;
    const int gbE  = (NE + B - 1) / B;
    const int gbNH = (NN * HD) / B;           // 12500 blocks, 8 nodes each

    k_init<<<gbN, B>>>(ei);
    k_hist<<<gbE, B>>>(ei);
    k_scan1<<<NB, SCAN_B>>>();
    k_scan23<<<gbN, B>>>();
    k_fill<<<gbE, B>>>(ei, ew);
    k_prep<<<gbNH, B>>>(x);

    k_layer1<<<gbNH, B>>>(W1, b1, W2);        // gather g_x -> g_Bh (fp16)
    k_layer2<<<gbNH, B>>>(b2, W3);            // deep-MLP gather g_Bh -> g_Ah (fp16)
    k_gather_pool<<<gbNH, B>>>(b3, batch);    // deep-MLP gather g_Ah + pool
    k_head<<<(NG + B - 1) / B, B>>>(lw, lb, out);
}